// round 4
// baseline (speedup 1.0000x reference)
#include <cuda_runtime.h>

// Problem constants
#define B_  256
#define T_  100
#define I_  2048
#define H_  2048
#define M_  (B_ * T_)   // 25600 GEMM rows

#define BM 128
#define BN 128
#define BK 16
#define TM 8
#define TN 4
#define NTHREADS 512
#define LDS 132   // padded smem row stride (floats), multiple of 4

// proj scratch: [M_, H_] fp32 = 200 MiB (device global, not an allocation)
__device__ float g_proj[(size_t)M_ * H_];

// ---------------------------------------------------------------------------
// Kernel A: proj = X @ W^T + bias, computed with error-free transformations
// (Dot2 / Ogita-Rump-Oishi): result is as if accumulated in ~fp64 and rounded
// once. TwoProd via FMA captures the product rounding; TwoSum captures the
// accumulation rounding; both feed a compensation register.
// ---------------------------------------------------------------------------
__global__ __launch_bounds__(NTHREADS, 1)
void lif_gemm_eft_kernel(const float* __restrict__ X,
                         const float* __restrict__ W,
                         const float* __restrict__ bias,
                         float* __restrict__ proj)
{
    __shared__ float As[BK * LDS];   // [k][m]
    __shared__ float Bs[BK * LDS];   // [k][n]

    const int bx = blockIdx.x;   // N tile (over H)
    const int by = blockIdx.y;   // M tile (over B*T)
    const int tid = threadIdx.x; // 0..511
    const int tx = tid & 31;     // 0..31 -> N (TN=4 each)
    const int ty = tid >> 5;     // 0..15 -> M (TM=8 each)

    const float* Xp = X + (size_t)by * BM * I_;
    const float* Wp = W + (size_t)bx * BN * I_;

    float s[TM][TN];   // primary sums
    float c[TM][TN];   // compensation
    #pragma unroll
    for (int i = 0; i < TM; i++)
        #pragma unroll
        for (int j = 0; j < TN; j++) { s[i][j] = 0.0f; c[i][j] = 0.0f; }

    for (int k0 = 0; k0 < I_; k0 += BK) {
        // Load 128x16 tiles: 512 float4 per tile, 1 per thread per tile.
        {
            int row  = tid >> 2;        // 0..127
            int col4 = tid & 3;         // 0..3
            float4 va = *(const float4*)(Xp + (size_t)row * I_ + k0 + col4 * 4);
            As[(col4 * 4 + 0) * LDS + row] = va.x;
            As[(col4 * 4 + 1) * LDS + row] = va.y;
            As[(col4 * 4 + 2) * LDS + row] = va.z;
            As[(col4 * 4 + 3) * LDS + row] = va.w;
            float4 vb = *(const float4*)(Wp + (size_t)row * I_ + k0 + col4 * 4);
            Bs[(col4 * 4 + 0) * LDS + row] = vb.x;
            Bs[(col4 * 4 + 1) * LDS + row] = vb.y;
            Bs[(col4 * 4 + 2) * LDS + row] = vb.z;
            Bs[(col4 * 4 + 3) * LDS + row] = vb.w;
        }
        __syncthreads();

        #pragma unroll
        for (int k = 0; k < BK; k++) {
            float a[TM], bv[TN];
            const float4* ap = (const float4*)&As[k * LDS + ty * TM];
            float4 a0 = ap[0], a1 = ap[1];
            a[0]=a0.x; a[1]=a0.y; a[2]=a0.z; a[3]=a0.w;
            a[4]=a1.x; a[5]=a1.y; a[6]=a1.z; a[7]=a1.w;
            float4 b0 = *(const float4*)&Bs[k * LDS + tx * TN];
            bv[0]=b0.x; bv[1]=b0.y; bv[2]=b0.z; bv[3]=b0.w;

            #pragma unroll
            for (int i = 0; i < TM; i++) {
                #pragma unroll
                for (int j = 0; j < TN; j++) {
                    // TwoProd: p + e == a*b exactly
                    float p = __fmul_rn(a[i], bv[j]);
                    float e = __fmaf_rn(a[i], bv[j], -p);
                    // TwoSum: t + err == s + p exactly
                    float t  = __fadd_rn(s[i][j], p);
                    float z  = __fsub_rn(t, s[i][j]);
                    float err = __fadd_rn(__fsub_rn(s[i][j], __fsub_rn(t, z)),
                                          __fsub_rn(p, z));
                    s[i][j] = t;
                    c[i][j] = __fadd_rn(c[i][j], __fadd_rn(err, e));
                }
            }
        }
        __syncthreads();
    }

    // Epilogue: fold compensation, add bias, store.
    #pragma unroll
    for (int i = 0; i < TM; i++) {
        size_t row = (size_t)by * BM + ty * TM + i;
        float* outp = proj + row * H_ + bx * BN + tx * TN;
        float r[TN];
        #pragma unroll
        for (int j = 0; j < TN; j++) {
            float v = __fadd_rn(s[i][j], c[i][j]);
            r[j] = __fadd_rn(v, bias[bx * BN + tx * TN + j]);
        }
        *(float4*)outp = make_float4(r[0], r[1], r[2], r[3]);
    }
}

// ---------------------------------------------------------------------------
// Kernel B: LIF scan over T. One thread per (b,h). Coalesced along h.
// Unfused mul+add to match XLA's separate multiply/add HLO ops.
// out layout: spikes [B,T,H] then h_final [B,H]
// ---------------------------------------------------------------------------
__global__ __launch_bounds__(256)
void lif_scan_kernel(const float* __restrict__ proj,
                     float* __restrict__ out)
{
    int idx = blockIdx.x * blockDim.x + threadIdx.x;  // 0 .. B*H-1
    if (idx >= B_ * H_) return;
    int b = idx / H_;
    int h = idx % H_;

    const size_t base = (size_t)b * T_ * H_ + h;
    float hstate = 0.0f;

    #pragma unroll 4
    for (int t = 0; t < T_; t++) {
        float p = proj[base + (size_t)t * H_];
        hstate = __fadd_rn(__fmul_rn(0.9f, hstate), p);
        float sp = (hstate >= 1.0f) ? 1.0f : 0.0f;
        out[base + (size_t)t * H_] = sp;
        hstate = __fmul_rn(hstate, __fsub_rn(1.0f, sp));
    }

    out[(size_t)B_ * T_ * H_ + (size_t)b * H_ + h] = hstate;
}

// ---------------------------------------------------------------------------
extern "C" void kernel_launch(void* const* d_in, const int* in_sizes, int n_in,
                              void* d_out, int out_size)
{
    const float* X    = (const float*)d_in[0];   // [256,100,2048]
    const float* W    = (const float*)d_in[1];   // [2048,2048]
    const float* bias = (const float*)d_in[2];   // [2048]
    float* out = (float*)d_out;

    float* proj;
    cudaGetSymbolAddress((void**)&proj, g_proj);

    dim3 ggrid(H_ / BN, M_ / BM);   // (16, 200)
    lif_gemm_eft_kernel<<<ggrid, NTHREADS>>>(X, W, bias, proj);

    int nthreads = B_ * H_;
    lif_scan_kernel<<<(nthreads + 255) / 256, 256>>>(proj, out);
}

// round 5
// speedup vs baseline: 1.0008x; 1.0008x over previous
#include <cuda_runtime.h>

// Problem constants
#define B_  256
#define T_  100
#define I_  2048
#define H_  2048
#define M_  (B_ * T_)   // 25600 GEMM rows

#define BM 128
#define BN 128
#define BK 16
#define TM 8
#define TN 4
#define NTHREADS 512
#define LDS 132   // padded smem row stride (floats), multiple of 4

// proj scratch: [M_, H_] fp32 = 200 MiB (device global, not an allocation)
__device__ float g_proj[(size_t)M_ * H_];

// ---------------------------------------------------------------------------
// Kernel A: proj = X @ W^T + bias, computed with error-free transformations
// (Dot2 / Ogita-Rump-Oishi): result is as if accumulated in ~fp64 and rounded
// once. TwoProd via FMA captures the product rounding; TwoSum captures the
// accumulation rounding; both feed a compensation register.
// ---------------------------------------------------------------------------
__global__ __launch_bounds__(NTHREADS, 1)
void lif_gemm_eft_kernel(const float* __restrict__ X,
                         const float* __restrict__ W,
                         const float* __restrict__ bias,
                         float* __restrict__ proj)
{
    __shared__ float As[BK * LDS];   // [k][m]
    __shared__ float Bs[BK * LDS];   // [k][n]

    const int bx = blockIdx.x;   // N tile (over H)
    const int by = blockIdx.y;   // M tile (over B*T)
    const int tid = threadIdx.x; // 0..511
    const int tx = tid & 31;     // 0..31 -> N (TN=4 each)
    const int ty = tid >> 5;     // 0..15 -> M (TM=8 each)

    const float* Xp = X + (size_t)by * BM * I_;
    const float* Wp = W + (size_t)bx * BN * I_;

    float s[TM][TN];   // primary sums
    float c[TM][TN];   // compensation
    #pragma unroll
    for (int i = 0; i < TM; i++)
        #pragma unroll
        for (int j = 0; j < TN; j++) { s[i][j] = 0.0f; c[i][j] = 0.0f; }

    for (int k0 = 0; k0 < I_; k0 += BK) {
        // Load 128x16 tiles: 512 float4 per tile, 1 per thread per tile.
        {
            int row  = tid >> 2;        // 0..127
            int col4 = tid & 3;         // 0..3
            float4 va = *(const float4*)(Xp + (size_t)row * I_ + k0 + col4 * 4);
            As[(col4 * 4 + 0) * LDS + row] = va.x;
            As[(col4 * 4 + 1) * LDS + row] = va.y;
            As[(col4 * 4 + 2) * LDS + row] = va.z;
            As[(col4 * 4 + 3) * LDS + row] = va.w;
            float4 vb = *(const float4*)(Wp + (size_t)row * I_ + k0 + col4 * 4);
            Bs[(col4 * 4 + 0) * LDS + row] = vb.x;
            Bs[(col4 * 4 + 1) * LDS + row] = vb.y;
            Bs[(col4 * 4 + 2) * LDS + row] = vb.z;
            Bs[(col4 * 4 + 3) * LDS + row] = vb.w;
        }
        __syncthreads();

        #pragma unroll
        for (int k = 0; k < BK; k++) {
            float a[TM], bv[TN];
            const float4* ap = (const float4*)&As[k * LDS + ty * TM];
            float4 a0 = ap[0], a1 = ap[1];
            a[0]=a0.x; a[1]=a0.y; a[2]=a0.z; a[3]=a0.w;
            a[4]=a1.x; a[5]=a1.y; a[6]=a1.z; a[7]=a1.w;
            float4 b0 = *(const float4*)&Bs[k * LDS + tx * TN];
            bv[0]=b0.x; bv[1]=b0.y; bv[2]=b0.z; bv[3]=b0.w;

            #pragma unroll
            for (int i = 0; i < TM; i++) {
                #pragma unroll
                for (int j = 0; j < TN; j++) {
                    // TwoProd: p + e == a*b exactly
                    float p = __fmul_rn(a[i], bv[j]);
                    float e = __fmaf_rn(a[i], bv[j], -p);
                    // TwoSum: t + err == s + p exactly
                    float t  = __fadd_rn(s[i][j], p);
                    float z  = __fsub_rn(t, s[i][j]);
                    float err = __fadd_rn(__fsub_rn(s[i][j], __fsub_rn(t, z)),
                                          __fsub_rn(p, z));
                    s[i][j] = t;
                    c[i][j] = __fadd_rn(c[i][j], __fadd_rn(err, e));
                }
            }
        }
        __syncthreads();
    }

    // Epilogue: fold compensation, add bias, store.
    #pragma unroll
    for (int i = 0; i < TM; i++) {
        size_t row = (size_t)by * BM + ty * TM + i;
        float* outp = proj + row * H_ + bx * BN + tx * TN;
        float r[TN];
        #pragma unroll
        for (int j = 0; j < TN; j++) {
            float v = __fadd_rn(s[i][j], c[i][j]);
            r[j] = __fadd_rn(v, bias[bx * BN + tx * TN + j]);
        }
        *(float4*)outp = make_float4(r[0], r[1], r[2], r[3]);
    }
}

// ---------------------------------------------------------------------------
// Kernel B: LIF scan over T. One thread per (b,h). Coalesced along h.
// Unfused mul+add to match XLA's separate multiply/add HLO ops.
// out layout: spikes [B,T,H] then h_final [B,H]
// ---------------------------------------------------------------------------
__global__ __launch_bounds__(256)
void lif_scan_kernel(const float* __restrict__ proj,
                     float* __restrict__ out)
{
    int idx = blockIdx.x * blockDim.x + threadIdx.x;  // 0 .. B*H-1
    if (idx >= B_ * H_) return;
    int b = idx / H_;
    int h = idx % H_;

    const size_t base = (size_t)b * T_ * H_ + h;
    float hstate = 0.0f;

    #pragma unroll 4
    for (int t = 0; t < T_; t++) {
        float p = proj[base + (size_t)t * H_];
        hstate = __fadd_rn(__fmul_rn(0.9f, hstate), p);
        float sp = (hstate >= 1.0f) ? 1.0f : 0.0f;
        out[base + (size_t)t * H_] = sp;
        hstate = __fmul_rn(hstate, __fsub_rn(1.0f, sp));
    }

    out[(size_t)B_ * T_ * H_ + (size_t)b * H_ + h] = hstate;
}

// ---------------------------------------------------------------------------
extern "C" void kernel_launch(void* const* d_in, const int* in_sizes, int n_in,
                              void* d_out, int out_size)
{
    const float* X    = (const float*)d_in[0];   // [256,100,2048]
    const float* W    = (const float*)d_in[1];   // [2048,2048]
    const float* bias = (const float*)d_in[2];   // [2048]
    float* out = (float*)d_out;

    float* proj;
    cudaGetSymbolAddress((void**)&proj, g_proj);

    dim3 ggrid(H_ / BN, M_ / BM);   // (16, 200)
    lif_gemm_eft_kernel<<<ggrid, NTHREADS>>>(X, W, bias, proj);

    int nthreads = B_ * H_;
    lif_scan_kernel<<<(nthreads + 255) / 256, 256>>>(proj, out);
}

// round 7
// speedup vs baseline: 2.0318x; 2.0301x over previous
#include <cuda_runtime.h>
#include <cstdint>

typedef unsigned long long u64;
typedef long long           i64;

// ---------------------------------------------------------------------------
#define B_   256
#define T_   100
#define I_   2048
#define H_   2048
#define M_   (B_ * T_)      // 25600

#define BM   64
#define BN   64
#define MT   (M_ / BM)      // 400
#define NT   (H_ / BN)      // 32
#define NCHUNK (I_ / 128)   // 16 K-chunks of 128 bytes

#define PLANE 8192          // 64 rows x 128 B per digit slice
#define STAGE (8 * PLANE)   // 4 A planes + 4 B planes = 64 KiB
#define DSMEM (2 * STAGE)   // 128 KiB double buffered

// Static device scratch (no allocations)
__device__ __align__(16) int8_t g_Xs[4ll * M_ * I_];   // 200 MiB digit planes
__device__ __align__(16) int8_t g_Ws[4ll * H_ * I_];   // 16 MiB
__device__ i64   g_SX[M_];
__device__ i64   g_SW[H_];
__device__ float g_sxf[M_];
__device__ float g_swf[H_];
__device__ float g_proj[(size_t)M_ * H_];              // 200 MiB

// ---------------------------------------------------------------------------
// helpers (all family-common PTX: sm_80-class, no tcgen05/TMA)
// ---------------------------------------------------------------------------
__device__ __forceinline__ uint32_t smem_u32(const void* p) {
    uint32_t a;
    asm("{ .reg .u64 t; cvta.to.shared.u64 t, %1; cvt.u32.u64 %0, t; }" : "=r"(a) : "l"(p));
    return a;
}
__device__ __forceinline__ uint32_t sw128(uint32_t o) { return o ^ ((o >> 3) & 0x70); }

__device__ __forceinline__ void ldsm4(uint32_t& r0, uint32_t& r1, uint32_t& r2, uint32_t& r3,
                                      uint32_t a) {
    asm volatile("ldmatrix.sync.aligned.m8n8.x4.shared.b16 {%0,%1,%2,%3}, [%4];"
                 : "=r"(r0), "=r"(r1), "=r"(r2), "=r"(r3) : "r"(a));
}
__device__ __forceinline__ void cpa16(uint32_t d, const void* s) {
    asm volatile("cp.async.cg.shared.global [%0], [%1], 16;" :: "r"(d), "l"(s));
}
#define CP_COMMIT() asm volatile("cp.async.commit_group;")
#define CP_WAIT1()  asm volatile("cp.async.wait_group 1;")
#define CP_WAIT0()  asm volatile("cp.async.wait_group 0;")

#define MMA(d, a, b) \
    asm volatile("mma.sync.aligned.m16n8k32.row.col.s32.s8.s8.s32 " \
                 "{%0,%1,%2,%3}, {%4,%5,%6,%7}, {%8,%9}, {%0,%1,%2,%3};" \
                 : "+r"((d)[0]), "+r"((d)[1]), "+r"((d)[2]), "+r"((d)[3]) \
                 : "r"((a)[0]), "r"((a)[1]), "r"((a)[2]), "r"((a)[3]), \
                   "r"((b)[0]), "r"((b)[1]))

// ---------------------------------------------------------------------------
// Split: per-row power-of-2 scale, 4 unsigned base-128 digits of (u+1)
// (all fp32 steps exact), plane layout dst[slice][row][k], per-row digit sum.
// ---------------------------------------------------------------------------
__global__ __launch_bounds__(256)
void split_kernel(const float* __restrict__ src, int8_t* __restrict__ dst,
                  i64* __restrict__ sumT, float* __restrict__ scl, i64 sstride)
{
    __shared__ float smax[256];
    __shared__ i64   ssum[256];
    __shared__ float s_inv;

    const int r = blockIdx.x;
    const int tid = threadIdx.x;
    const float* row = src + (size_t)r * I_;

    float mx = 0.0f;
    #pragma unroll
    for (int it = 0; it < I_ / 256; it++) mx = fmaxf(mx, fabsf(row[tid + it * 256]));
    smax[tid] = mx;
    __syncthreads();
    for (int s = 128; s > 0; s >>= 1) {
        if (tid < s) smax[tid] = fmaxf(smax[tid], smax[tid + s]);
        __syncthreads();
    }
    if (tid == 0) {
        int e = 0;
        if (smax[0] > 0.0f) frexpf(smax[0], &e);   // max = f*2^e, f in [0.5,1)
        s_inv = ldexpf(1.0f, -e);
        scl[r] = ldexpf(1.0f, e - 27);
    }
    __syncthreads();
    const float sinv = s_inv;

    i64 acc = 0;
    #pragma unroll
    for (int it = 0; it < I_ / 256; it++) {
        int k = tid + it * 256;
        float u  = row[k] * sinv;                 // exact, |u| < 1
        float t0 = u * 64.0f;   float f0 = floorf(t0); float r1 = t0 - f0;
        float t1 = r1 * 128.0f; float f1 = floorf(t1); float r2 = t1 - f1;
        float t2 = r2 * 128.0f; float f2 = floorf(t2); float r3 = t2 - f2;
        float f3 = floorf(r3 * 128.0f);
        int c0 = (int)f0 + 64;                    // [0,127]
        int c1 = (int)f1, c2 = (int)f2, c3 = (int)f3;

        acc += (i64)(((c0 * 128 + c1) * 128 + c2) * 128 + c3);

        i64 base = (i64)r * I_ + k;
        dst[0 * sstride + base] = (int8_t)c0;
        dst[1 * sstride + base] = (int8_t)c1;
        dst[2 * sstride + base] = (int8_t)c2;
        dst[3 * sstride + base] = (int8_t)c3;
    }

    ssum[tid] = acc;
    __syncthreads();
    for (int s = 128; s > 0; s >>= 1) {
        if (tid < s) ssum[tid] += ssum[tid + s];
        __syncthreads();
    }
    if (tid == 0) sumT[r] = ssum[0];
}

// ---------------------------------------------------------------------------
// GEMM: warp-level int8 mma.sync, 15 digit pairs -> 6 exact s32 accumulators,
// exact mod-2^64 recombination. CTA tile 64x64, 8 warps (4M x 2N), warp tile
// m16 x n32. cp.async double-buffered K-chunks of 128B with SW128 swizzle.
// ---------------------------------------------------------------------------
__global__ __launch_bounds__(256, 1)
void lif_gemm_imma_kernel(const float* __restrict__ bias, float* __restrict__ proj)
{
    extern __shared__ int8_t smem[];
    const uint32_t sb = smem_u32(smem);
    const int tid  = threadIdx.x;
    const int lane = tid & 31;
    const int wid  = tid >> 5;
    const int wm   = wid >> 1;    // 0..3 -> M group (16 rows)
    const int wn   = wid & 1;     // 0..1 -> N group (32 cols)
    const int bx = blockIdx.x;    // N tile
    const int by = blockIdx.y;    // M tile

    const int q  = lane >> 3;
    const int l7 = lane & 7;

    int D[6][4][4];
    #pragma unroll
    for (int s = 0; s < 6; s++)
        #pragma unroll
        for (int nt = 0; nt < 4; nt++)
            #pragma unroll
            for (int e = 0; e < 4; e++) D[s][nt][e] = 0;

#define LOAD_CHUNK(c) do {                                                        \
    uint32_t stg = sb + ((c) & 1) * STAGE;                                        \
    _Pragma("unroll")                                                             \
    for (int v = 0; v < 16; v++) {                                                \
        int id = v * 256 + tid;                                                   \
        int slice = (id >> 9) & 3;                                                \
        int idx = id & 511;                                                       \
        int row = idx >> 3, x = idx & 7;                                          \
        uint32_t dst = stg + ((id >> 11) ? 4 * PLANE : 0) + slice * PLANE         \
                     + sw128((uint32_t)(row * 128 + x * 16));                     \
        const int8_t* src = (id >> 11)                                            \
            ? (g_Ws + (i64)slice * H_ * I_ + (i64)(bx * BN + row) * I_ + (c) * 128 + x * 16) \
            : (g_Xs + (i64)slice * M_ * I_ + (i64)(by * BM + row) * I_ + (c) * 128 + x * 16); \
        cpa16(dst, src);                                                          \
    }                                                                             \
    CP_COMMIT();                                                                  \
} while (0)

#define PP(i, j, s) {                                                             \
    _Pragma("unroll")                                                             \
    for (int nt = 0; nt < 4; nt++) MMA(D[s][nt], A[i], Bt[j][nt]);                \
}

#define COMPUTE_CHUNK(c) do {                                                     \
    uint32_t stg = sb + ((c) & 1) * STAGE;                                        \
    _Pragma("unroll")                                                             \
    for (int ks = 0; ks < 4; ks++) {                                              \
        uint32_t A[4][4];                                                         \
        _Pragma("unroll")                                                         \
        for (int sl = 0; sl < 4; sl++) {                                          \
            int row = wm * 16 + ((q & 1) << 3) + l7;                              \
            uint32_t ad = stg + sl * PLANE                                        \
                        + sw128((uint32_t)(row * 128 + ks * 32 + (q >> 1) * 16)); \
            ldsm4(A[sl][0], A[sl][1], A[sl][2], A[sl][3], ad);                    \
        }                                                                         \
        uint32_t Bt[4][4][2];                                                     \
        _Pragma("unroll")                                                         \
        for (int sl = 0; sl < 4; sl++) {                                          \
            _Pragma("unroll")                                                     \
            for (int g = 0; g < 2; g++) {                                         \
                int n = wn * 32 + g * 16 + ((q >> 1) << 3) + l7;                  \
                uint32_t bd = stg + 4 * PLANE + sl * PLANE                        \
                            + sw128((uint32_t)(n * 128 + ks * 32 + (q & 1) * 16));\
                uint32_t r0, r1, r2, r3;                                          \
                ldsm4(r0, r1, r2, r3, bd);                                        \
                Bt[sl][2 * g][0] = r0; Bt[sl][2 * g][1] = r1;                     \
                Bt[sl][2 * g + 1][0] = r2; Bt[sl][2 * g + 1][1] = r3;             \
            }                                                                     \
        }                                                                         \
        PP(0,0,0) PP(0,1,1) PP(1,0,1) PP(0,2,2) PP(1,1,2) PP(2,0,2)               \
        PP(0,3,3) PP(1,2,3) PP(2,1,3) PP(3,0,3) PP(1,3,4) PP(2,2,4)               \
        PP(3,1,4) PP(2,3,5) PP(3,2,5)                                             \
    }                                                                             \
} while (0)

    LOAD_CHUNK(0);
    #pragma unroll 1
    for (int c = 0; c < NCHUNK; c++) {
        if (c + 1 < NCHUNK) {
            LOAD_CHUNK(c + 1);
            CP_WAIT1();
        } else {
            CP_WAIT0();
        }
        __syncthreads();
        COMPUTE_CHUNK(c);
        __syncthreads();
    }

    // ---- epilogue: exact recombination ----
    // D layout (m16n8 s32): d0,d1 -> row lane/4, cols 2(lane%4)+{0,1}; d2,d3 -> row+8.
    const int mrow0 = by * BM + wm * 16 + (lane >> 2);
    const int col0  = bx * BN + wn * 32 + 2 * (lane & 3);

    #pragma unroll
    for (int half = 0; half < 2; half++) {
        int m = mrow0 + 8 * half;
        i64 SXm = g_SX[m];
        double sx = (double)g_sxf[m];
        float* orow = proj + (size_t)m * H_ + col0;
        #pragma unroll
        for (int nt = 0; nt < 4; nt++) {
            float v[2];
            #pragma unroll
            for (int dj = 0; dj < 2; dj++) {
                int h = col0 + 8 * nt + dj;
                int e = 2 * half + dj;
                u64 P = ((u64)(uint32_t)D[0][nt][e] << 42)
                      + ((u64)(uint32_t)D[1][nt][e] << 35)
                      + ((u64)(uint32_t)D[2][nt][e] << 28)
                      + ((u64)(uint32_t)D[3][nt][e] << 21)
                      + ((u64)(uint32_t)D[4][nt][e] << 14)
                      + ((u64)(uint32_t)D[5][nt][e] << 7);
                // true*2^54 = P - 2^27*(SX+SW) + K*2^54; K*2^54 == 0 mod 2^64
                i64 Pp = (i64)(P - ((u64)(SXm + g_SW[h]) << 27));
                double sc = sx * (double)g_swf[h];   // product of powers of 2: exact
                v[dj] = (float)((double)Pp * sc + (double)bias[h]);
            }
            *(float2*)(orow + 8 * nt) = make_float2(v[0], v[1]);
        }
    }
#undef LOAD_CHUNK
#undef COMPUTE_CHUNK
#undef PP
}

// ---------------------------------------------------------------------------
// LIF scan (measured: ~67us, DRAM 70%)
// ---------------------------------------------------------------------------
__global__ __launch_bounds__(256)
void lif_scan_kernel(const float* __restrict__ proj, float* __restrict__ out)
{
    int idx = blockIdx.x * blockDim.x + threadIdx.x;
    if (idx >= B_ * H_) return;
    int b = idx / H_;
    int h = idx % H_;
    const size_t base = (size_t)b * T_ * H_ + h;
    float hs = 0.0f;
    #pragma unroll 4
    for (int t = 0; t < T_; t++) {
        float p = proj[base + (size_t)t * H_];
        hs = __fadd_rn(__fmul_rn(0.9f, hs), p);
        float sp = (hs >= 1.0f) ? 1.0f : 0.0f;
        out[base + (size_t)t * H_] = sp;
        hs = __fmul_rn(hs, __fsub_rn(1.0f, sp));
    }
    out[(size_t)B_ * T_ * H_ + (size_t)b * H_ + h] = hs;
}

// ---------------------------------------------------------------------------
extern "C" void kernel_launch(void* const* d_in, const int* in_sizes, int n_in,
                              void* d_out, int out_size)
{
    const float* X    = (const float*)d_in[0];
    const float* W    = (const float*)d_in[1];
    const float* bias = (const float*)d_in[2];
    float* out = (float*)d_out;

    int8_t *Xs, *Ws;
    i64 *SX, *SW;
    float *sxf, *swf, *proj;
    cudaGetSymbolAddress((void**)&Xs, g_Xs);
    cudaGetSymbolAddress((void**)&Ws, g_Ws);
    cudaGetSymbolAddress((void**)&SX, g_SX);
    cudaGetSymbolAddress((void**)&SW, g_SW);
    cudaGetSymbolAddress((void**)&sxf, g_sxf);
    cudaGetSymbolAddress((void**)&swf, g_swf);
    cudaGetSymbolAddress((void**)&proj, g_proj);

    cudaFuncSetAttribute(lif_gemm_imma_kernel,
                         cudaFuncAttributeMaxDynamicSharedMemorySize, DSMEM);

    // digit splits
    split_kernel<<<M_, 256>>>(X, Xs, SX, sxf, (i64)M_ * I_);
    split_kernel<<<H_, 256>>>(W, Ws, SW, swf, (i64)H_ * I_);

    // int8 warp-MMA GEMM with exact recombination
    dim3 ggrid(NT, MT);   // (32, 400): N fastest -> A tiles shared in L2
    lif_gemm_imma_kernel<<<ggrid, 256, DSMEM>>>(bias, proj);

    // LIF scan
    lif_scan_kernel<<<(B_ * H_ + 255) / 256, 256>>>(proj, out);
}